// round 13
// baseline (speedup 1.0000x reference)
#include <cuda_runtime.h>
#include <cuda_fp16.h>
#include <cstdint>
#include <cstddef>

// Problem constants
#define B_   4
#define L_   4096
#define E_   1024
#define H_   16
#define D_   64
#define C_   128
#define NC_  (L_ / C_)
#define MTOT (B_ * L_)
#define EPS_ 1e-5f

// ---------------------------------------------------------------------------
// Scratch
// ---------------------------------------------------------------------------
__device__ float g_phi_q[(size_t)B_ * L_ * E_];
__device__ float g_phi_k[(size_t)B_ * L_ * E_];
__device__ float g_v    [(size_t)B_ * L_ * E_];
__device__ float g_S[(size_t)B_ * H_ * NC_ * D_ * D_];
__device__ float g_z[(size_t)B_ * H_ * NC_ * D_];

__device__ __half g_x_hi[(size_t)MTOT * E_];
__device__ __half g_x_lo[(size_t)MTOT * E_];
__device__ __half g_attn_hi[(size_t)MTOT * E_];
__device__ __half g_w_hi[4][(size_t)E_ * E_];   // q,k,v contiguous = [3072][1024]

// ---------------------------------------------------------------------------
// PTX helpers
// ---------------------------------------------------------------------------
__device__ __forceinline__ void mma_f16(float* c, const uint32_t* a, const uint32_t* b)
{
    asm volatile(
        "mma.sync.aligned.m16n8k16.row.col.f32.f16.f16.f32 "
        "{%0,%1,%2,%3}, {%4,%5,%6,%7}, {%8,%9}, {%0,%1,%2,%3};\n"
        : "+f"(c[0]), "+f"(c[1]), "+f"(c[2]), "+f"(c[3])
        : "r"(a[0]), "r"(a[1]), "r"(a[2]), "r"(a[3]), "r"(b[0]), "r"(b[1]));
}

__device__ __forceinline__ void ldm_x4(uint32_t* r, uint32_t addr)
{
    asm volatile("ldmatrix.sync.aligned.m8n8.x4.shared.b16 {%0,%1,%2,%3}, [%4];\n"
                 : "=r"(r[0]), "=r"(r[1]), "=r"(r[2]), "=r"(r[3]) : "r"(addr));
}
__device__ __forceinline__ void ldm_x4t(uint32_t* r, uint32_t addr)
{
    asm volatile("ldmatrix.sync.aligned.m8n8.x4.trans.shared.b16 {%0,%1,%2,%3}, [%4];\n"
                 : "=r"(r[0]), "=r"(r[1]), "=r"(r[2]), "=r"(r[3]) : "r"(addr));
}
__device__ __forceinline__ void ldm_x2t(uint32_t* r, uint32_t addr)
{
    asm volatile("ldmatrix.sync.aligned.m8n8.x2.trans.shared.b16 {%0,%1}, [%2];\n"
                 : "=r"(r[0]), "=r"(r[1]) : "r"(addr));
}
__device__ __forceinline__ uint32_t packh(float a, float b)
{
    __half2 h = __floats2half2_rn(a, b);
    return *(uint32_t*)&h;
}
__device__ __forceinline__ void cp16h(__half* dst, const __half* src)
{
    uint32_t d = (uint32_t)__cvta_generic_to_shared(dst);
    asm volatile("cp.async.cg.shared.global [%0], [%1], 16;\n" :: "r"(d), "l"(src));
}
__device__ __forceinline__ void cp_commit() { asm volatile("cp.async.commit_group;\n"); }
__device__ __forceinline__ void cp_wait1()  { asm volatile("cp.async.wait_group 1;\n"); }
__device__ __forceinline__ void cp_wait0()  { asm volatile("cp.async.wait_group 0;\n"); }

// ---------------------------------------------------------------------------
// Splits
// ---------------------------------------------------------------------------
__global__ __launch_bounds__(256)
void split_kernel(const float* __restrict__ in, __half* __restrict__ hi,
                  __half* __restrict__ lo, int n4)
{
    int i = blockIdx.x * 256 + threadIdx.x;
    if (i >= n4) return;
    float4 v = ((const float4*)in)[i];
    union { __half b[4]; uint2 u; } ph, pl;
    const float* vp = (const float*)&v;
#pragma unroll
    for (int j = 0; j < 4; j++) {
        __half hb = __float2half_rn(vp[j]);
        ph.b[j] = hb;
        pl.b[j] = __float2half_rn(vp[j] - __half2float(hb));
    }
    ((uint2*)hi)[i] = ph.u;
    ((uint2*)lo)[i] = pl.u;
}

__global__ __launch_bounds__(256)
void wsplit_kernel(const float* __restrict__ w0, const float* __restrict__ w1,
                   const float* __restrict__ w2, const float* __restrict__ w3,
                   __half* __restrict__ hi_base, int n4)
{
    int i = blockIdx.x * 256 + threadIdx.x;
    if (i >= n4) return;
    const int sel = blockIdx.y;
    const float* src = (sel == 0) ? w0 : (sel == 1) ? w1 : (sel == 2) ? w2 : w3;
    __half* hi = hi_base + (size_t)sel * E_ * E_;
    float4 v = ((const float4*)src)[i];
    union { __half b[4]; uint2 u; } ph;
    ph.b[0] = __float2half_rn(v.x); ph.b[1] = __float2half_rn(v.y);
    ph.b[2] = __float2half_rn(v.z); ph.b[3] = __float2half_rn(v.w);
    ((uint2*)hi)[i] = ph.u;
}

// ---------------------------------------------------------------------------
// Tensor-core GEMM.
//   MODE 0: out-projection, 1-term (Ahi only) + bias.
//   MODE 1: fused QKV (N=3072); q,k blocks use 2-term (Ahi+Alo), v blocks 1-term;
//           elu+1 on q,k.
// ---------------------------------------------------------------------------
#define SROW 40
#define STAGE_ELEMS (3 * 128 * SROW)     // Ahi, Alo, Bhi
#define GEMM_SMEM (2 * STAGE_ELEMS * 2)

template <int MODE>
__global__ __launch_bounds__(256, 2)
void gemm_f16split(const __half* __restrict__ Ahi, const __half* __restrict__ Alo,
                   const __half* __restrict__ Bhi,
                   const float* __restrict__ bias,
                   float* __restrict__ out0, float* __restrict__ out1, float* __restrict__ out2,
                   int M, int N, int K)
{
    extern __shared__ __half smem[];

    const int tid  = threadIdx.x;
    const int bm   = blockIdx.y * 128;
    const int bn   = blockIdx.x * 128;
    const int warp = tid >> 5, lane = tid & 31;
    const int wm   = (warp & 3) * 32;
    const int wn   = (warp >> 2) * 64;
    const int gid  = lane >> 2;
    const int tig  = lane & 3;

    const int KT = K / 32;
    const bool use_lo = (MODE == 1) ? (((int)blockIdx.x >> 3) < 2) : false;

    __half* stage0 = smem;
    __half* stage1 = smem + STAGE_ELEMS;
    const uint32_t st0s = (uint32_t)__cvta_generic_to_shared(stage0);
    const uint32_t st1s = st0s + STAGE_ELEMS * 2;
    const uint32_t ALO_OFF = 128 * SROW * 2;
    const uint32_t BHI_OFF = 2 * 128 * SROW * 2;

    const int lidx = lane & 7;
    const int lmat = lane >> 3;
    int aoff[2];
#pragma unroll
    for (int mi = 0; mi < 2; mi++)
        aoff[mi] = (wm + mi * 16 + ((lmat & 1) << 3) + lidx) * SROW + ((lmat >> 1) << 3);
    int boff[4];
#pragma unroll
    for (int p = 0; p < 4; p++)
        boff[p] = (wn + p * 16 + ((lmat >> 1) << 3) + lidx) * SROW + ((lmat & 1) << 3);

    auto issue = [&](int kt, int s) {
        __half* sAh = s ? stage1 : stage0;
        __half* sAl = sAh + 128 * SROW;
        __half* sBh = sAl + 128 * SROW;
        const int kbase = kt * 32;
#pragma unroll
        for (int c = 0; c < 2; c++) {
            int q   = tid + c * 256;
            int row = q >> 2;
            int kc  = (q & 3) << 3;
            const size_t ga = (size_t)(bm + row) * K + kbase + kc;
            const size_t gb = (size_t)(bn + row) * K + kbase + kc;
            cp16h(sAh + row * SROW + kc, Ahi + ga);
            if (use_lo) cp16h(sAl + row * SROW + kc, Alo + ga);
            cp16h(sBh + row * SROW + kc, Bhi + gb);
        }
        cp_commit();
    };

    float acc[2][8][4];
#pragma unroll
    for (int mi = 0; mi < 2; mi++)
#pragma unroll
        for (int ni = 0; ni < 8; ni++)
#pragma unroll
            for (int j = 0; j < 4; j++) acc[mi][ni][j] = 0.f;

    issue(0, 0);
    issue(1, 1);

    for (int kt = 0; kt < KT; kt++) {
        if (kt + 1 < KT) cp_wait1(); else cp_wait0();
        __syncthreads();

        const uint32_t sb = (kt & 1) ? st1s : st0s;

#pragma unroll
        for (int ks = 0; ks < 2; ks++) {
            const uint32_t kofs = (uint32_t)(ks * 16) * 2;
            uint32_t ahi[2][4], alo[2][4];
#pragma unroll
            for (int mi = 0; mi < 2; mi++) {
                const uint32_t ab = sb + (uint32_t)aoff[mi] * 2 + kofs;
                ldm_x4(ahi[mi], ab);
                if (use_lo) ldm_x4(alo[mi], ab + ALO_OFF);
            }
#pragma unroll
            for (int p = 0; p < 4; p++) {
                uint32_t bh4[4];
                const uint32_t bb = sb + BHI_OFF + (uint32_t)boff[p] * 2 + kofs;
                ldm_x4(bh4, bb);
#pragma unroll
                for (int sub = 0; sub < 2; sub++) {
                    const uint32_t bh2[2] = { bh4[sub * 2], bh4[sub * 2 + 1] };
                    const int ni = p * 2 + sub;
#pragma unroll
                    for (int mi = 0; mi < 2; mi++) {
                        mma_f16(acc[mi][ni], ahi[mi], bh2);
                        if (use_lo) mma_f16(acc[mi][ni], alo[mi], bh2);
                    }
                }
            }
        }
        __syncthreads();
        if (kt + 2 < KT) issue(kt + 2, kt & 1);
    }

    float* dst;
    int col_base, nOut;
    bool do_elu = false;
    if (MODE == 1) {
        const int seg = (int)blockIdx.x >> 3;
        dst = (seg == 0) ? out0 : (seg == 1) ? out1 : out2;
        col_base = ((int)blockIdx.x & 7) * 128;
        nOut = 1024;
        do_elu = (seg < 2);
    } else {
        dst = out0; col_base = bn; nOut = N;
    }

#pragma unroll
    for (int mi = 0; mi < 2; mi++) {
#pragma unroll
        for (int ni = 0; ni < 8; ni++) {
            const int row = bm + wm + mi * 16 + gid;
            const int col = col_base + wn + ni * 8 + tig * 2;
            float v0 = acc[mi][ni][0], v1 = acc[mi][ni][1];
            float v2 = acc[mi][ni][2], v3 = acc[mi][ni][3];
            if (MODE == 1) {
                if (do_elu) {
                    v0 = (v0 > 0.f) ? (v0 + 1.f) : expf(v0);
                    v1 = (v1 > 0.f) ? (v1 + 1.f) : expf(v1);
                    v2 = (v2 > 0.f) ? (v2 + 1.f) : expf(v2);
                    v3 = (v3 > 0.f) ? (v3 + 1.f) : expf(v3);
                }
            } else {
                v0 += bias[col]; v1 += bias[col + 1];
                v2 += bias[col]; v3 += bias[col + 1];
            }
            *(float2*)(dst + (size_t)row * nOut + col)       = make_float2(v0, v1);
            *(float2*)(dst + (size_t)(row + 8) * nOut + col) = make_float2(v2, v3);
        }
    }
}

// ---------------------------------------------------------------------------
// Chunk-local states (verified R12)
// ---------------------------------------------------------------------------
#define CLROW 72
#define OFF_CKH 0
#define OFF_CKL (OFF_CKH + 128 * CLROW)
#define OFF_CVH (OFF_CKL + 128 * CLROW)
#define CL_SMEM ((OFF_CVH + 128 * CLROW) * 2)

__global__ __launch_bounds__(256, 2)
void chunk_local_tc(const float* __restrict__ pk, const float* __restrict__ vv,
                    float* __restrict__ Sloc, float* __restrict__ zloc)
{
    extern __shared__ __half cls[];
    const uint32_t sbase = (uint32_t)__cvta_generic_to_shared(cls);

    const int tid  = threadIdx.x;
    const int warp = tid >> 5, lane = tid & 31;
    const int g    = lane >> 2, t = lane & 3;
    const int lidx = lane & 7,  lmat = lane >> 3;

    const int c = blockIdx.x, h = blockIdx.y, b = blockIdx.z;
    const size_t base = ((size_t)b * L_ + (size_t)c * C_) * E_ + (size_t)h * D_;
    const float* pkb = pk + base;
    const float* vb  = vv + base;

    for (int i = tid; i < 128 * 16; i += 256) {
        const int row = i >> 4;
        const int c4  = (i & 15) << 2;
        float4 kv = *(const float4*)(pkb + (size_t)row * E_ + c4);
        float4 wv = *(const float4*)(vb  + (size_t)row * E_ + c4);
        union { __half bx[4]; uint2 u; } ph, pl, pvx;
        const float* kp = (const float*)&kv;
#pragma unroll
        for (int j = 0; j < 4; j++) {
            __half hb = __float2half_rn(kp[j]);
            ph.bx[j] = hb;
            pl.bx[j] = __float2half_rn(kp[j] - __half2float(hb));
        }
        pvx.bx[0] = __float2half_rn(wv.x); pvx.bx[1] = __float2half_rn(wv.y);
        pvx.bx[2] = __float2half_rn(wv.z); pvx.bx[3] = __float2half_rn(wv.w);
        *(uint2*)&cls[OFF_CKH + row * CLROW + c4] = ph.u;
        *(uint2*)&cls[OFF_CKL + row * CLROW + c4] = pl.u;
        *(uint2*)&cls[OFF_CVH + row * CLROW + c4] = pvx.u;
    }
    __syncthreads();

    const int wm_ = (warp & 3) * 16;
    const int wn_ = (warp >> 2) * 32;

    float acc[4][4];
#pragma unroll
    for (int nt = 0; nt < 4; nt++)
#pragma unroll
        for (int q = 0; q < 4; q++) acc[nt][q] = 0.f;

#pragma unroll
    for (int ks = 0; ks < 8; ks++) {
        const int k0 = ks * 16;
        const uint32_t arow = (uint32_t)(k0 + ((lmat >> 1) << 3) + lidx);
        const uint32_t acol = (uint32_t)(wm_ + ((lmat & 1) << 3));
        const uint32_t aaddr = sbase + (uint32_t)((OFF_CKH + arow * CLROW + acol) * 2);
        uint32_t ah[4], al[4];
        ldm_x4t(ah, aaddr);
        ldm_x4t(al, aaddr + (OFF_CKL - OFF_CKH) * 2);

        const uint32_t vaddr0 = sbase +
            (uint32_t)((OFF_CVH + (k0 + (lane & 15)) * CLROW + wn_) * 2);
#pragma unroll
        for (int nt = 0; nt < 4; nt++) {
            uint32_t bh2[2];
            ldm_x2t(bh2, vaddr0 + nt * 16);
            mma_f16(acc[nt], ah, bh2);
            mma_f16(acc[nt], al, bh2);
        }
    }

    float* Sout = Sloc + ((((size_t)b * H_ + h) * NC_ + c) * D_ * D_);
    const int row0 = wm_ + g, row1 = row0 + 8;
#pragma unroll
    for (int nt = 0; nt < 4; nt++) {
        const int col = wn_ + nt * 8 + 2 * t;
        *(float2*)(Sout + (size_t)row0 * D_ + col) = make_float2(acc[nt][0], acc[nt][1]);
        *(float2*)(Sout + (size_t)row1 * D_ + col) = make_float2(acc[nt][2], acc[nt][3]);
    }

    if (tid < D_) {
        float s = 0.f;
#pragma unroll 8
        for (int r = 0; r < C_; r++)
            s += __half2float(cls[OFF_CKH + r * CLROW + tid]) +
                 __half2float(cls[OFF_CKL + r * CLROW + tid]);
        zloc[(((size_t)b * H_ + h) * NC_ + c) * D_ + tid] = s;
    }
}

// ---------------------------------------------------------------------------
// Exclusive prefix (verified R12)
// ---------------------------------------------------------------------------
__global__ __launch_bounds__(256)
void prefix_kernel(float* __restrict__ S, float* __restrict__ z)
{
    const int bh = blockIdx.x;
    const int i  = blockIdx.y * 256 + threadIdx.x;
    float* Sb = S + (size_t)bh * NC_ * D_ * D_;

    float run = 0.f;
#pragma unroll
    for (int c = 0; c < NC_; c++) {
        float* p = Sb + (size_t)c * D_ * D_ + i;
        float loc = *p;
        *p = run;
        run += loc;
    }

    if (blockIdx.y == 0 && threadIdx.x < D_) {
        float* zb = z + (size_t)bh * NC_ * D_;
        float zr = 0.f;
#pragma unroll
        for (int c = 0; c < NC_; c++) {
            float loc = zb[(size_t)c * D_ + threadIdx.x];
            zb[(size_t)c * D_ + threadIdx.x] = zr;
            zr += loc;
        }
    }
}

// ---------------------------------------------------------------------------
// Chunk output — R11 internals; epilogue now emits attn_hi only (1-term out-proj)
// ---------------------------------------------------------------------------
#define QROW 72
#define OFF_QHI 0
#define OFF_QLO (OFF_QHI + 128 * QROW)
#define OFF_KHI (OFF_QLO + 128 * QROW)
#define OFF_VHI (OFF_KHI + 128 * QROW)
#define OFF_STHI (OFF_VHI + 128 * QROW)
#define OFF_Z    (OFF_STHI + 64 * QROW)
#define CO_SMEM ((OFF_Z + 128) * 2)

__global__ __launch_bounds__(256, 2)
void chunk_out_kernel(const float* __restrict__ pq, const float* __restrict__ pk,
                      const float* __restrict__ vv, const float* __restrict__ S,
                      const float* __restrict__ z,
                      __half* __restrict__ attn_hi)
{
    extern __shared__ __half cs[];
    const uint32_t sbase = (uint32_t)__cvta_generic_to_shared(cs);

    const int tid  = threadIdx.x;
    const int warp = tid >> 5, lane = tid & 31;
    const int g    = lane >> 2, t = lane & 3;
    const int lidx = lane & 7,  lmat = lane >> 3;

    const int c = blockIdx.x, h = blockIdx.y, b = blockIdx.z;
    const size_t base = ((size_t)b * L_ + (size_t)c * C_) * E_ + (size_t)h * D_;
    const float* pqb = pq + base;
    const float* pkb = pk + base;
    const float* vb  = vv + base;

    for (int i = tid; i < 128 * 16; i += 256) {
        const int row = i >> 4;
        const int c4  = (i & 15) << 2;
        float4 qv = *(const float4*)(pqb + (size_t)row * E_ + c4);
        float4 kv = *(const float4*)(pkb + (size_t)row * E_ + c4);
        float4 wv = *(const float4*)(vb  + (size_t)row * E_ + c4);
        union { __half bx[4]; uint2 u; } ph, pl, pkx, pvx;
        const float* qp = (const float*)&qv;
#pragma unroll
        for (int j = 0; j < 4; j++) {
            __half hb = __float2half_rn(qp[j]);
            ph.bx[j] = hb;
            pl.bx[j] = __float2half_rn(qp[j] - __half2float(hb));
        }
        pkx.bx[0] = __float2half_rn(kv.x); pkx.bx[1] = __float2half_rn(kv.y);
        pkx.bx[2] = __float2half_rn(kv.z); pkx.bx[3] = __float2half_rn(kv.w);
        pvx.bx[0] = __float2half_rn(wv.x); pvx.bx[1] = __float2half_rn(wv.y);
        pvx.bx[2] = __float2half_rn(wv.z); pvx.bx[3] = __float2half_rn(wv.w);
        *(uint2*)&cs[OFF_QHI + row * QROW + c4] = ph.u;
        *(uint2*)&cs[OFF_QLO + row * QROW + c4] = pl.u;
        *(uint2*)&cs[OFF_KHI + row * QROW + c4] = pkx.u;
        *(uint2*)&cs[OFF_VHI + row * QROW + c4] = pvx.u;
    }
    {
        const float* Sb = S + (((size_t)b * H_ + h) * NC_ + c) * D_ * D_;
        for (int i = tid; i < 64 * 16; i += 256) {
            const int r  = i >> 4;
            const int c4 = (i & 15) << 2;
            float4 sv = *(const float4*)(Sb + (size_t)r * D_ + c4);
            const float* sp = (const float*)&sv;
#pragma unroll
            for (int j = 0; j < 4; j++)
                cs[OFF_STHI + (c4 + j) * QROW + r] = __float2half_rn(sp[j]);
        }
        if (tid < 64) {
            const float* zbp = z + (((size_t)b * H_ + h) * NC_ + c) * D_;
            ((float*)(cs + OFF_Z))[tid] = zbp[tid];
        }
    }
    __syncthreads();

    const uint32_t aoff_b =
        (uint32_t)(((16 * warp + ((lmat & 1) << 3) + lidx) * QROW + ((lmat >> 1) << 3)) * 2);
    uint32_t aqh[4][4], aql[4][4];
#pragma unroll
    for (int ks = 0; ks < 4; ks++) {
        const uint32_t qa = sbase + OFF_QHI * 2 + aoff_b + ks * 32;
        ldm_x4(aqh[ks], qa);
        ldm_x4(aql[ks], qa + (OFF_QLO - OFF_QHI) * 2);
    }

    float acc[8][4];
#pragma unroll
    for (int nt = 0; nt < 8; nt++)
#pragma unroll
        for (int q = 0; q < 4; q++) acc[nt][q] = 0.f;

#pragma unroll
    for (int ks = 0; ks < 4; ks++) {
#pragma unroll
        for (int p4 = 0; p4 < 4; p4++) {
            const uint32_t bb = sbase + OFF_STHI * 2 +
                (uint32_t)(((p4 * 16 + ((lmat >> 1) << 3) + lidx) * QROW + ((lmat & 1) << 3)) * 2)
                + ks * 32;
            uint32_t bh4[4];
            ldm_x4(bh4, bb);
#pragma unroll
            for (int sub = 0; sub < 2; sub++) {
                const uint32_t bh2[2] = { bh4[sub * 2], bh4[sub * 2 + 1] };
                mma_f16(acc[2 * p4 + sub], aqh[ks], bh2);
                mma_f16(acc[2 * p4 + sub], aql[ks], bh2);
            }
        }
    }

    const int row0 = 16 * warp + g;
    const int row1 = row0 + 8;
    float pg = 0.f, pg8 = 0.f;
    const uint32_t vrow_lane = (uint32_t)(lane & 15);

    for (int p = 0; p <= warp; p++) {
        float mC2[2][4];
#pragma unroll
        for (int sub = 0; sub < 2; sub++)
#pragma unroll
            for (int q = 0; q < 4; q++) mC2[sub][q] = 0.f;

#pragma unroll
        for (int ks = 0; ks < 4; ks++) {
            const uint32_t bb = sbase + OFF_KHI * 2 +
                (uint32_t)(((p * 16 + ((lmat >> 1) << 3) + lidx) * QROW + ((lmat & 1) << 3)) * 2)
                + ks * 32;
            uint32_t bh4[4];
            ldm_x4(bh4, bb);
#pragma unroll
            for (int sub = 0; sub < 2; sub++) {
                const uint32_t bh2[2] = { bh4[sub * 2], bh4[sub * 2 + 1] };
                mma_f16(mC2[sub], aqh[ks], bh2);
                mma_f16(mC2[sub], aql[ks], bh2);
            }
        }

        if (p == warp) {
#pragma unroll
            for (int sub = 0; sub < 2; sub++) {
                const int c0 = 16 * p + 8 * sub + 2 * t;
                if (c0 > row0)     mC2[sub][0] = 0.f;
                if (c0 + 1 > row0) mC2[sub][1] = 0.f;
                if (c0 > row1)     mC2[sub][2] = 0.f;
                if (c0 + 1 > row1) mC2[sub][3] = 0.f;
            }
        }
        pg  += mC2[0][0] + mC2[0][1] + mC2[1][0] + mC2[1][1];
        pg8 += mC2[0][2] + mC2[0][3] + mC2[1][2] + mC2[1][3];

        uint32_t mh[4], ml[4];
#pragma unroll
        for (int q = 0; q < 4; q++) {
            const int sub = q >> 1;
            const int lohalf = (q & 1) * 2;
            float v0 = mC2[sub][lohalf], v1 = mC2[sub][lohalf + 1];
            float h0 = __half2float(__float2half_rn(v0));
            float h1 = __half2float(__float2half_rn(v1));
            mh[q] = packh(h0, h1);
            ml[q] = packh(v0 - h0, v1 - h1);
        }

        const uint32_t vbase = sbase + OFF_VHI * 2 +
            (uint32_t)(((p * 16 + vrow_lane) * QROW) * 2);
#pragma unroll
        for (int nt = 0; nt < 8; nt++) {
            uint32_t vh2[2];
            ldm_x2t(vh2, vbase + nt * 16);
            mma_f16(acc[nt], mh, vh2);
            mma_f16(acc[nt], ml, vh2);
        }
    }

    pg  += __shfl_xor_sync(0xffffffffu, pg, 1);
    pg  += __shfl_xor_sync(0xffffffffu, pg, 2);
    pg8 += __shfl_xor_sync(0xffffffffu, pg8, 1);
    pg8 += __shfl_xor_sync(0xffffffffu, pg8, 2);

    float dqv = 0.f;
    if (lane < 16) {
        const int r = 16 * warp + lane;
        const float* zf = (const float*)(cs + OFF_Z);
#pragma unroll 8
        for (int k = 0; k < 64; k++) {
            float qv = __half2float(cs[OFF_QHI + r * QROW + k]) +
                       __half2float(cs[OFF_QLO + r * QROW + k]);
            dqv += qv * zf[k];
        }
    }
    const float dq0 = __shfl_sync(0xffffffffu, dqv, g);
    const float dq8 = __shfl_sync(0xffffffffu, dqv, g + 8);
    const float rs0 = 1.f / (pg  + dq0 + EPS_);
    const float rs1 = 1.f / (pg8 + dq8 + EPS_);

    __half* obh = attn_hi + base;
#pragma unroll
    for (int nt = 0; nt < 8; nt++) {
        const int col = 8 * nt + 2 * t;
        *(uint32_t*)(obh + (size_t)row0 * E_ + col) =
            packh(acc[nt][0] * rs0, acc[nt][1] * rs0);
        *(uint32_t*)(obh + (size_t)row1 * E_ + col) =
            packh(acc[nt][2] * rs1, acc[nt][3] * rs1);
    }
}

// ---------------------------------------------------------------------------
// Launch
// ---------------------------------------------------------------------------
extern "C" void kernel_launch(void* const* d_in, const int* in_sizes, int n_in,
                              void* d_out, int out_size)
{
    const float* x  = (const float*)d_in[0];
    const float* Wq = (const float*)d_in[1];
    const float* Wk = (const float*)d_in[2];
    const float* Wv = (const float*)d_in[3];
    const float* Wo = (const float*)d_in[4];
    const float* bo = (const float*)d_in[5];
    float* out = (float*)d_out;

    float *phi_q, *phi_k, *vbuf, *Sb, *zb;
    __half *xhi, *xlo, *ahi, *whi;
    cudaGetSymbolAddress((void**)&phi_q, g_phi_q);
    cudaGetSymbolAddress((void**)&phi_k, g_phi_k);
    cudaGetSymbolAddress((void**)&vbuf,  g_v);
    cudaGetSymbolAddress((void**)&Sb,    g_S);
    cudaGetSymbolAddress((void**)&zb,    g_z);
    cudaGetSymbolAddress((void**)&xhi,   g_x_hi);
    cudaGetSymbolAddress((void**)&xlo,   g_x_lo);
    cudaGetSymbolAddress((void**)&ahi,   g_attn_hi);
    cudaGetSymbolAddress((void**)&whi,   g_w_hi);

    (void)cudaFuncSetAttribute(chunk_local_tc,
                               cudaFuncAttributeMaxDynamicSharedMemorySize, CL_SMEM);
    (void)cudaFuncSetAttribute(chunk_out_kernel,
                               cudaFuncAttributeMaxDynamicSharedMemorySize, CO_SMEM);
    (void)cudaFuncSetAttribute(gemm_f16split<0>,
                               cudaFuncAttributeMaxDynamicSharedMemorySize, GEMM_SMEM);
    (void)cudaFuncSetAttribute(gemm_f16split<1>,
                               cudaFuncAttributeMaxDynamicSharedMemorySize, GEMM_SMEM);

    // ---- splits ----
    const int nx4 = (MTOT * E_) / 4;
    split_kernel<<<(nx4 + 255) / 256, 256>>>(x, xhi, xlo, nx4);
    const int nw4 = (E_ * E_) / 4;
    const size_t wsz = (size_t)E_ * E_;
    dim3 gws((nw4 + 255) / 256, 4);
    wsplit_kernel<<<gws, 256>>>(Wq, Wk, Wv, Wo, whi, nw4);

    // ---- fused QKV projection: q,k 2-term; v 1-term ----
    dim3 gqkv(3 * E_ / 128, MTOT / 128), gb(256);
    gemm_f16split<1><<<gqkv, gb, GEMM_SMEM>>>(xhi, xlo, whi, nullptr,
                                              phi_q, phi_k, vbuf, MTOT, 3 * E_, E_);

    // ---- chunked linear attention ----
    dim3 gc(NC_, H_, B_);
    chunk_local_tc<<<gc, 256, CL_SMEM>>>(phi_k, vbuf, Sb, zb);
    dim3 gp(B_ * H_, 16);
    prefix_kernel<<<gp, 256>>>(Sb, zb);
    chunk_out_kernel<<<gc, 256, CO_SMEM>>>(phi_q, phi_k, vbuf, Sb, zb, ahi);

    // ---- output projection (1-term) + bias ----
    dim3 gout(E_ / 128, MTOT / 128);
    gemm_f16split<0><<<gout, gb, GEMM_SMEM>>>(ahi, ahi, whi + 3 * wsz,
                                              bo, out, nullptr, nullptr, MTOT, E_, E_);
}

// round 15
// speedup vs baseline: 1.3056x; 1.3056x over previous
#include <cuda_runtime.h>
#include <cuda_fp16.h>
#include <cstdint>
#include <cstddef>

// Problem constants
#define B_   4
#define L_   4096
#define E_   1024
#define H_   16
#define D_   64
#define C_   128
#define NC_  (L_ / C_)
#define MTOT (B_ * L_)
#define EPS_ 1e-5f

// ---------------------------------------------------------------------------
// Scratch
// ---------------------------------------------------------------------------
__device__ float g_phi_q[(size_t)B_ * L_ * E_];
__device__ float g_phi_k[(size_t)B_ * L_ * E_];
__device__ float g_v    [(size_t)B_ * L_ * E_];
__device__ float g_S[(size_t)B_ * H_ * NC_ * D_ * D_];
__device__ float g_z[(size_t)B_ * H_ * NC_ * D_];

__device__ __half g_x_hi[(size_t)MTOT * E_];
__device__ __half g_x_lo[(size_t)MTOT * E_];
__device__ __half g_attn_hi[(size_t)MTOT * E_];
__device__ __half g_w_hi[4][(size_t)E_ * E_];   // q,k,v contiguous = [3072][1024]

// ---------------------------------------------------------------------------
// PTX helpers
// ---------------------------------------------------------------------------
__device__ __forceinline__ void mma_f16(float* c, const uint32_t* a, const uint32_t* b)
{
    asm volatile(
        "mma.sync.aligned.m16n8k16.row.col.f32.f16.f16.f32 "
        "{%0,%1,%2,%3}, {%4,%5,%6,%7}, {%8,%9}, {%0,%1,%2,%3};\n"
        : "+f"(c[0]), "+f"(c[1]), "+f"(c[2]), "+f"(c[3])
        : "r"(a[0]), "r"(a[1]), "r"(a[2]), "r"(a[3]), "r"(b[0]), "r"(b[1]));
}

__device__ __forceinline__ void ldm_x4(uint32_t* r, uint32_t addr)
{
    asm volatile("ldmatrix.sync.aligned.m8n8.x4.shared.b16 {%0,%1,%2,%3}, [%4];\n"
                 : "=r"(r[0]), "=r"(r[1]), "=r"(r[2]), "=r"(r[3]) : "r"(addr));
}
__device__ __forceinline__ void ldm_x4t(uint32_t* r, uint32_t addr)
{
    asm volatile("ldmatrix.sync.aligned.m8n8.x4.trans.shared.b16 {%0,%1,%2,%3}, [%4];\n"
                 : "=r"(r[0]), "=r"(r[1]), "=r"(r[2]), "=r"(r[3]) : "r"(addr));
}
__device__ __forceinline__ void ldm_x2t(uint32_t* r, uint32_t addr)
{
    asm volatile("ldmatrix.sync.aligned.m8n8.x2.trans.shared.b16 {%0,%1}, [%2];\n"
                 : "=r"(r[0]), "=r"(r[1]) : "r"(addr));
}
__device__ __forceinline__ uint32_t packh(float a, float b)
{
    __half2 h = __floats2half2_rn(a, b);
    return *(uint32_t*)&h;
}
__device__ __forceinline__ void cp16h(__half* dst, const __half* src)
{
    uint32_t d = (uint32_t)__cvta_generic_to_shared(dst);
    asm volatile("cp.async.cg.shared.global [%0], [%1], 16;\n" :: "r"(d), "l"(src));
}
__device__ __forceinline__ void cp_commit() { asm volatile("cp.async.commit_group;\n"); }
__device__ __forceinline__ void cp_wait1()  { asm volatile("cp.async.wait_group 1;\n"); }
__device__ __forceinline__ void cp_wait0()  { asm volatile("cp.async.wait_group 0;\n"); }

// ---------------------------------------------------------------------------
// Splits
// ---------------------------------------------------------------------------
__global__ __launch_bounds__(256)
void split_kernel(const float* __restrict__ in, __half* __restrict__ hi,
                  __half* __restrict__ lo, int n4)
{
    int i = blockIdx.x * 256 + threadIdx.x;
    if (i >= n4) return;
    float4 v = ((const float4*)in)[i];
    union { __half b[4]; uint2 u; } ph, pl;
    const float* vp = (const float*)&v;
#pragma unroll
    for (int j = 0; j < 4; j++) {
        __half hb = __float2half_rn(vp[j]);
        ph.b[j] = hb;
        pl.b[j] = __float2half_rn(vp[j] - __half2float(hb));
    }
    ((uint2*)hi)[i] = ph.u;
    ((uint2*)lo)[i] = pl.u;
}

__global__ __launch_bounds__(256)
void wsplit_kernel(const float* __restrict__ w0, const float* __restrict__ w1,
                   const float* __restrict__ w2, const float* __restrict__ w3,
                   __half* __restrict__ hi_base, int n4)
{
    int i = blockIdx.x * 256 + threadIdx.x;
    if (i >= n4) return;
    const int sel = blockIdx.y;
    const float* src = (sel == 0) ? w0 : (sel == 1) ? w1 : (sel == 2) ? w2 : w3;
    __half* hi = hi_base + (size_t)sel * E_ * E_;
    float4 v = ((const float4*)src)[i];
    union { __half b[4]; uint2 u; } ph;
    ph.b[0] = __float2half_rn(v.x); ph.b[1] = __float2half_rn(v.y);
    ph.b[2] = __float2half_rn(v.z); ph.b[3] = __float2half_rn(v.w);
    ((uint2*)hi)[i] = ph.u;
}

// ---------------------------------------------------------------------------
// Tensor-core GEMM — fully static per MODE (no runtime branches in hot loop).
//   MODE 0: out-projection, 1-term + bias.
//   MODE 1: fused QK (N=2048), 2-term, elu+1 on both outputs.
//   MODE 2: v-projection, 1-term, plain.
// ---------------------------------------------------------------------------
#define SROW 40
#define STAGE_ELEMS (3 * 128 * SROW)     // Ahi, Alo, Bhi
#define GEMM_SMEM (2 * STAGE_ELEMS * 2)

template <int MODE>
__global__ __launch_bounds__(256, 2)
void gemm_f16split(const __half* __restrict__ Ahi, const __half* __restrict__ Alo,
                   const __half* __restrict__ Bhi,
                   const float* __restrict__ bias,
                   float* __restrict__ out0, float* __restrict__ out1,
                   int M, int N, int K)
{
    extern __shared__ __half smem[];
    constexpr bool USE_LO = (MODE == 1);

    const int tid  = threadIdx.x;
    const int bm   = blockIdx.y * 128;
    const int bn   = blockIdx.x * 128;
    const int warp = tid >> 5, lane = tid & 31;
    const int wm   = (warp & 3) * 32;
    const int wn   = (warp >> 2) * 64;
    const int gid  = lane >> 2;
    const int tig  = lane & 3;

    const int KT = K / 32;

    __half* stage0 = smem;
    __half* stage1 = smem + STAGE_ELEMS;
    const uint32_t st0s = (uint32_t)__cvta_generic_to_shared(stage0);
    const uint32_t st1s = st0s + STAGE_ELEMS * 2;
    const uint32_t ALO_OFF = 128 * SROW * 2;
    const uint32_t BHI_OFF = 2 * 128 * SROW * 2;

    const int lidx = lane & 7;
    const int lmat = lane >> 3;
    int aoff[2];
#pragma unroll
    for (int mi = 0; mi < 2; mi++)
        aoff[mi] = (wm + mi * 16 + ((lmat & 1) << 3) + lidx) * SROW + ((lmat >> 1) << 3);
    int boff[4];
#pragma unroll
    for (int p = 0; p < 4; p++)
        boff[p] = (wn + p * 16 + ((lmat >> 1) << 3) + lidx) * SROW + ((lmat & 1) << 3);

    auto issue = [&](int kt, int s) {
        __half* sAh = s ? stage1 : stage0;
        __half* sAl = sAh + 128 * SROW;
        __half* sBh = sAl + 128 * SROW;
        const int kbase = kt * 32;
#pragma unroll
        for (int c = 0; c < 2; c++) {
            int q   = tid + c * 256;
            int row = q >> 2;
            int kc  = (q & 3) << 3;
            const size_t ga = (size_t)(bm + row) * K + kbase + kc;
            const size_t gb = (size_t)(bn + row) * K + kbase + kc;
            cp16h(sAh + row * SROW + kc, Ahi + ga);
            if (USE_LO) cp16h(sAl + row * SROW + kc, Alo + ga);
            cp16h(sBh + row * SROW + kc, Bhi + gb);
        }
        cp_commit();
    };

    float acc[2][8][4];
#pragma unroll
    for (int mi = 0; mi < 2; mi++)
#pragma unroll
        for (int ni = 0; ni < 8; ni++)
#pragma unroll
            for (int j = 0; j < 4; j++) acc[mi][ni][j] = 0.f;

    issue(0, 0);
    issue(1, 1);

    for (int kt = 0; kt < KT; kt++) {
        if (kt + 1 < KT) cp_wait1(); else cp_wait0();
        __syncthreads();

        const uint32_t sb = (kt & 1) ? st1s : st0s;

#pragma unroll
        for (int ks = 0; ks < 2; ks++) {
            const uint32_t kofs = (uint32_t)(ks * 16) * 2;
            uint32_t ahi[2][4], alo[2][4];
#pragma unroll
            for (int mi = 0; mi < 2; mi++) {
                const uint32_t ab = sb + (uint32_t)aoff[mi] * 2 + kofs;
                ldm_x4(ahi[mi], ab);
                if (USE_LO) ldm_x4(alo[mi], ab + ALO_OFF);
            }
#pragma unroll
            for (int p = 0; p < 4; p++) {
                uint32_t bh4[4];
                const uint32_t bb = sb + BHI_OFF + (uint32_t)boff[p] * 2 + kofs;
                ldm_x4(bh4, bb);
#pragma unroll
                for (int sub = 0; sub < 2; sub++) {
                    const uint32_t bh2[2] = { bh4[sub * 2], bh4[sub * 2 + 1] };
                    const int ni = p * 2 + sub;
#pragma unroll
                    for (int mi = 0; mi < 2; mi++) {
                        mma_f16(acc[mi][ni], ahi[mi], bh2);
                        if (USE_LO) mma_f16(acc[mi][ni], alo[mi], bh2);
                    }
                }
            }
        }
        __syncthreads();
        if (kt + 2 < KT) issue(kt + 2, kt & 1);
    }

    float* dst;
    int col_base, nOut;
    if (MODE == 1) {
        const int seg = (int)blockIdx.x >> 3;            // 0 = q, 1 = k
        dst = seg ? out1 : out0;
        col_base = ((int)blockIdx.x & 7) * 128;
        nOut = 1024;
    } else {
        dst = out0; col_base = bn; nOut = N;
    }

#pragma unroll
    for (int mi = 0; mi < 2; mi++) {
#pragma unroll
        for (int ni = 0; ni < 8; ni++) {
            const int row = bm + wm + mi * 16 + gid;
            const int col = col_base + wn + ni * 8 + tig * 2;
            float v0 = acc[mi][ni][0], v1 = acc[mi][ni][1];
            float v2 = acc[mi][ni][2], v3 = acc[mi][ni][3];
            if (MODE == 1) {
                v0 = (v0 > 0.f) ? (v0 + 1.f) : expf(v0);
                v1 = (v1 > 0.f) ? (v1 + 1.f) : expf(v1);
                v2 = (v2 > 0.f) ? (v2 + 1.f) : expf(v2);
                v3 = (v3 > 0.f) ? (v3 + 1.f) : expf(v3);
            }
            if (MODE == 0) {
                v0 += bias[col]; v1 += bias[col + 1];
                v2 += bias[col]; v3 += bias[col + 1];
            }
            *(float2*)(dst + (size_t)row * nOut + col)       = make_float2(v0, v1);
            *(float2*)(dst + (size_t)(row + 8) * nOut + col) = make_float2(v2, v3);
        }
    }
}

// ---------------------------------------------------------------------------
// Chunk-local states (verified R12)
// ---------------------------------------------------------------------------
#define CLROW 72
#define OFF_CKH 0
#define OFF_CKL (OFF_CKH + 128 * CLROW)
#define OFF_CVH (OFF_CKL + 128 * CLROW)
#define CL_SMEM ((OFF_CVH + 128 * CLROW) * 2)

__global__ __launch_bounds__(256, 2)
void chunk_local_tc(const float* __restrict__ pk, const float* __restrict__ vv,
                    float* __restrict__ Sloc, float* __restrict__ zloc)
{
    extern __shared__ __half cls[];
    const uint32_t sbase = (uint32_t)__cvta_generic_to_shared(cls);

    const int tid  = threadIdx.x;
    const int warp = tid >> 5, lane = tid & 31;
    const int g    = lane >> 2, t = lane & 3;
    const int lidx = lane & 7,  lmat = lane >> 3;

    const int c = blockIdx.x, h = blockIdx.y, b = blockIdx.z;
    const size_t base = ((size_t)b * L_ + (size_t)c * C_) * E_ + (size_t)h * D_;
    const float* pkb = pk + base;
    const float* vb  = vv + base;

    for (int i = tid; i < 128 * 16; i += 256) {
        const int row = i >> 4;
        const int c4  = (i & 15) << 2;
        float4 kv = *(const float4*)(pkb + (size_t)row * E_ + c4);
        float4 wv = *(const float4*)(vb  + (size_t)row * E_ + c4);
        union { __half bx[4]; uint2 u; } ph, pl, pvx;
        const float* kp = (const float*)&kv;
#pragma unroll
        for (int j = 0; j < 4; j++) {
            __half hb = __float2half_rn(kp[j]);
            ph.bx[j] = hb;
            pl.bx[j] = __float2half_rn(kp[j] - __half2float(hb));
        }
        pvx.bx[0] = __float2half_rn(wv.x); pvx.bx[1] = __float2half_rn(wv.y);
        pvx.bx[2] = __float2half_rn(wv.z); pvx.bx[3] = __float2half_rn(wv.w);
        *(uint2*)&cls[OFF_CKH + row * CLROW + c4] = ph.u;
        *(uint2*)&cls[OFF_CKL + row * CLROW + c4] = pl.u;
        *(uint2*)&cls[OFF_CVH + row * CLROW + c4] = pvx.u;
    }
    __syncthreads();

    const int wm_ = (warp & 3) * 16;
    const int wn_ = (warp >> 2) * 32;

    float acc[4][4];
#pragma unroll
    for (int nt = 0; nt < 4; nt++)
#pragma unroll
        for (int q = 0; q < 4; q++) acc[nt][q] = 0.f;

#pragma unroll
    for (int ks = 0; ks < 8; ks++) {
        const int k0 = ks * 16;
        const uint32_t arow = (uint32_t)(k0 + ((lmat >> 1) << 3) + lidx);
        const uint32_t acol = (uint32_t)(wm_ + ((lmat & 1) << 3));
        const uint32_t aaddr = sbase + (uint32_t)((OFF_CKH + arow * CLROW + acol) * 2);
        uint32_t ah[4], al[4];
        ldm_x4t(ah, aaddr);
        ldm_x4t(al, aaddr + (OFF_CKL - OFF_CKH) * 2);

        const uint32_t vaddr0 = sbase +
            (uint32_t)((OFF_CVH + (k0 + (lane & 15)) * CLROW + wn_) * 2);
#pragma unroll
        for (int nt = 0; nt < 4; nt++) {
            uint32_t bh2[2];
            ldm_x2t(bh2, vaddr0 + nt * 16);
            mma_f16(acc[nt], ah, bh2);
            mma_f16(acc[nt], al, bh2);
        }
    }

    float* Sout = Sloc + ((((size_t)b * H_ + h) * NC_ + c) * D_ * D_);
    const int row0 = wm_ + g, row1 = row0 + 8;
#pragma unroll
    for (int nt = 0; nt < 4; nt++) {
        const int col = wn_ + nt * 8 + 2 * t;
        *(float2*)(Sout + (size_t)row0 * D_ + col) = make_float2(acc[nt][0], acc[nt][1]);
        *(float2*)(Sout + (size_t)row1 * D_ + col) = make_float2(acc[nt][2], acc[nt][3]);
    }

    if (tid < D_) {
        float s = 0.f;
#pragma unroll 8
        for (int r = 0; r < C_; r++)
            s += __half2float(cls[OFF_CKH + r * CLROW + tid]) +
                 __half2float(cls[OFF_CKL + r * CLROW + tid]);
        zloc[(((size_t)b * H_ + h) * NC_ + c) * D_ + tid] = s;
    }
}

// ---------------------------------------------------------------------------
// Exclusive prefix (verified R12)
// ---------------------------------------------------------------------------
__global__ __launch_bounds__(256)
void prefix_kernel(float* __restrict__ S, float* __restrict__ z)
{
    const int bh = blockIdx.x;
    const int i  = blockIdx.y * 256 + threadIdx.x;
    float* Sb = S + (size_t)bh * NC_ * D_ * D_;

    float run = 0.f;
#pragma unroll
    for (int c = 0; c < NC_; c++) {
        float* p = Sb + (size_t)c * D_ * D_ + i;
        float loc = *p;
        *p = run;
        run += loc;
    }

    if (blockIdx.y == 0 && threadIdx.x < D_) {
        float* zb = z + (size_t)bh * NC_ * D_;
        float zr = 0.f;
#pragma unroll
        for (int c = 0; c < NC_; c++) {
            float loc = zb[(size_t)c * D_ + threadIdx.x];
            zb[(size_t)c * D_ + threadIdx.x] = zr;
            zr += loc;
        }
    }
}

// ---------------------------------------------------------------------------
// Chunk output — verified R11 internals; emits attn_hi only (verified R13)
// ---------------------------------------------------------------------------
#define QROW 72
#define OFF_QHI 0
#define OFF_QLO (OFF_QHI + 128 * QROW)
#define OFF_KHI (OFF_QLO + 128 * QROW)
#define OFF_VHI (OFF_KHI + 128 * QROW)
#define OFF_STHI (OFF_VHI + 128 * QROW)
#define OFF_Z    (OFF_STHI + 64 * QROW)
#define CO_SMEM ((OFF_Z + 128) * 2)

__global__ __launch_bounds__(256, 2)
void chunk_out_kernel(const float* __restrict__ pq, const float* __restrict__ pk,
                      const float* __restrict__ vv, const float* __restrict__ S,
                      const float* __restrict__ z,
                      __half* __restrict__ attn_hi)
{
    extern __shared__ __half cs[];
    const uint32_t sbase = (uint32_t)__cvta_generic_to_shared(cs);

    const int tid  = threadIdx.x;
    const int warp = tid >> 5, lane = tid & 31;
    const int g    = lane >> 2, t = lane & 3;
    const int lidx = lane & 7,  lmat = lane >> 3;

    const int c = blockIdx.x, h = blockIdx.y, b = blockIdx.z;
    const size_t base = ((size_t)b * L_ + (size_t)c * C_) * E_ + (size_t)h * D_;
    const float* pqb = pq + base;
    const float* pkb = pk + base;
    const float* vb  = vv + base;

    for (int i = tid; i < 128 * 16; i += 256) {
        const int row = i >> 4;
        const int c4  = (i & 15) << 2;
        float4 qv = *(const float4*)(pqb + (size_t)row * E_ + c4);
        float4 kv = *(const float4*)(pkb + (size_t)row * E_ + c4);
        float4 wv = *(const float4*)(vb  + (size_t)row * E_ + c4);
        union { __half bx[4]; uint2 u; } ph, pl, pkx, pvx;
        const float* qp = (const float*)&qv;
#pragma unroll
        for (int j = 0; j < 4; j++) {
            __half hb = __float2half_rn(qp[j]);
            ph.bx[j] = hb;
            pl.bx[j] = __float2half_rn(qp[j] - __half2float(hb));
        }
        pkx.bx[0] = __float2half_rn(kv.x); pkx.bx[1] = __float2half_rn(kv.y);
        pkx.bx[2] = __float2half_rn(kv.z); pkx.bx[3] = __float2half_rn(kv.w);
        pvx.bx[0] = __float2half_rn(wv.x); pvx.bx[1] = __float2half_rn(wv.y);
        pvx.bx[2] = __float2half_rn(wv.z); pvx.bx[3] = __float2half_rn(wv.w);
        *(uint2*)&cs[OFF_QHI + row * QROW + c4] = ph.u;
        *(uint2*)&cs[OFF_QLO + row * QROW + c4] = pl.u;
        *(uint2*)&cs[OFF_KHI + row * QROW + c4] = pkx.u;
        *(uint2*)&cs[OFF_VHI + row * QROW + c4] = pvx.u;
    }
    {
        const float* Sb = S + (((size_t)b * H_ + h) * NC_ + c) * D_ * D_;
        for (int i = tid; i < 64 * 16; i += 256) {
            const int r  = i >> 4;
            const int c4 = (i & 15) << 2;
            float4 sv = *(const float4*)(Sb + (size_t)r * D_ + c4);
            const float* sp = (const float*)&sv;
#pragma unroll
            for (int j = 0; j < 4; j++)
                cs[OFF_STHI + (c4 + j) * QROW + r] = __float2half_rn(sp[j]);
        }
        if (tid < 64) {
            const float* zbp = z + (((size_t)b * H_ + h) * NC_ + c) * D_;
            ((float*)(cs + OFF_Z))[tid] = zbp[tid];
        }
    }
    __syncthreads();

    const uint32_t aoff_b =
        (uint32_t)(((16 * warp + ((lmat & 1) << 3) + lidx) * QROW + ((lmat >> 1) << 3)) * 2);
    uint32_t aqh[4][4], aql[4][4];
#pragma unroll
    for (int ks = 0; ks < 4; ks++) {
        const uint32_t qa = sbase + OFF_QHI * 2 + aoff_b + ks * 32;
        ldm_x4(aqh[ks], qa);
        ldm_x4(aql[ks], qa + (OFF_QLO - OFF_QHI) * 2);
    }

    float acc[8][4];
#pragma unroll
    for (int nt = 0; nt < 8; nt++)
#pragma unroll
        for (int q = 0; q < 4; q++) acc[nt][q] = 0.f;

#pragma unroll
    for (int ks = 0; ks < 4; ks++) {
#pragma unroll
        for (int p4 = 0; p4 < 4; p4++) {
            const uint32_t bb = sbase + OFF_STHI * 2 +
                (uint32_t)(((p4 * 16 + ((lmat >> 1) << 3) + lidx) * QROW + ((lmat & 1) << 3)) * 2)
                + ks * 32;
            uint32_t bh4[4];
            ldm_x4(bh4, bb);
#pragma unroll
            for (int sub = 0; sub < 2; sub++) {
                const uint32_t bh2[2] = { bh4[sub * 2], bh4[sub * 2 + 1] };
                mma_f16(acc[2 * p4 + sub], aqh[ks], bh2);
                mma_f16(acc[2 * p4 + sub], aql[ks], bh2);
            }
        }
    }

    const int row0 = 16 * warp + g;
    const int row1 = row0 + 8;
    float pg = 0.f, pg8 = 0.f;
    const uint32_t vrow_lane = (uint32_t)(lane & 15);

    for (int p = 0; p <= warp; p++) {
        float mC2[2][4];
#pragma unroll
        for (int sub = 0; sub < 2; sub++)
#pragma unroll
            for (int q = 0; q < 4; q++) mC2[sub][q] = 0.f;

#pragma unroll
        for (int ks = 0; ks < 4; ks++) {
            const uint32_t bb = sbase + OFF_KHI * 2 +
                (uint32_t)(((p * 16 + ((lmat >> 1) << 3) + lidx) * QROW + ((lmat & 1) << 3)) * 2)
                + ks * 32;
            uint32_t bh4[4];
            ldm_x4(bh4, bb);
#pragma unroll
            for (int sub = 0; sub < 2; sub++) {
                const uint32_t bh2[2] = { bh4[sub * 2], bh4[sub * 2 + 1] };
                mma_f16(mC2[sub], aqh[ks], bh2);
                mma_f16(mC2[sub], aql[ks], bh2);
            }
        }

        if (p == warp) {
#pragma unroll
            for (int sub = 0; sub < 2; sub++) {
                const int c0 = 16 * p + 8 * sub + 2 * t;
                if (c0 > row0)     mC2[sub][0] = 0.f;
                if (c0 + 1 > row0) mC2[sub][1] = 0.f;
                if (c0 > row1)     mC2[sub][2] = 0.f;
                if (c0 + 1 > row1) mC2[sub][3] = 0.f;
            }
        }
        pg  += mC2[0][0] + mC2[0][1] + mC2[1][0] + mC2[1][1];
        pg8 += mC2[0][2] + mC2[0][3] + mC2[1][2] + mC2[1][3];

        uint32_t mh[4], ml[4];
#pragma unroll
        for (int q = 0; q < 4; q++) {
            const int sub = q >> 1;
            const int lohalf = (q & 1) * 2;
            float v0 = mC2[sub][lohalf], v1 = mC2[sub][lohalf + 1];
            float h0 = __half2float(__float2half_rn(v0));
            float h1 = __half2float(__float2half_rn(v1));
            mh[q] = packh(h0, h1);
            ml[q] = packh(v0 - h0, v1 - h1);
        }

        const uint32_t vbase = sbase + OFF_VHI * 2 +
            (uint32_t)(((p * 16 + vrow_lane) * QROW) * 2);
#pragma unroll
        for (int nt = 0; nt < 8; nt++) {
            uint32_t vh2[2];
            ldm_x2t(vh2, vbase + nt * 16);
            mma_f16(acc[nt], mh, vh2);
            mma_f16(acc[nt], ml, vh2);
        }
    }

    pg  += __shfl_xor_sync(0xffffffffu, pg, 1);
    pg  += __shfl_xor_sync(0xffffffffu, pg, 2);
    pg8 += __shfl_xor_sync(0xffffffffu, pg8, 1);
    pg8 += __shfl_xor_sync(0xffffffffu, pg8, 2);

    float dqv = 0.f;
    if (lane < 16) {
        const int r = 16 * warp + lane;
        const float* zf = (const float*)(cs + OFF_Z);
#pragma unroll 8
        for (int k = 0; k < 64; k++) {
            float qv = __half2float(cs[OFF_QHI + r * QROW + k]) +
                       __half2float(cs[OFF_QLO + r * QROW + k]);
            dqv += qv * zf[k];
        }
    }
    const float dq0 = __shfl_sync(0xffffffffu, dqv, g);
    const float dq8 = __shfl_sync(0xffffffffu, dqv, g + 8);
    const float rs0 = 1.f / (pg  + dq0 + EPS_);
    const float rs1 = 1.f / (pg8 + dq8 + EPS_);

    __half* obh = attn_hi + base;
#pragma unroll
    for (int nt = 0; nt < 8; nt++) {
        const int col = 8 * nt + 2 * t;
        *(uint32_t*)(obh + (size_t)row0 * E_ + col) =
            packh(acc[nt][0] * rs0, acc[nt][1] * rs0);
        *(uint32_t*)(obh + (size_t)row1 * E_ + col) =
            packh(acc[nt][2] * rs1, acc[nt][3] * rs1);
    }
}

// ---------------------------------------------------------------------------
// Launch
// ---------------------------------------------------------------------------
extern "C" void kernel_launch(void* const* d_in, const int* in_sizes, int n_in,
                              void* d_out, int out_size)
{
    const float* x  = (const float*)d_in[0];
    const float* Wq = (const float*)d_in[1];
    const float* Wk = (const float*)d_in[2];
    const float* Wv = (const float*)d_in[3];
    const float* Wo = (const float*)d_in[4];
    const float* bo = (const float*)d_in[5];
    float* out = (float*)d_out;

    float *phi_q, *phi_k, *vbuf, *Sb, *zb;
    __half *xhi, *xlo, *ahi, *whi;
    cudaGetSymbolAddress((void**)&phi_q, g_phi_q);
    cudaGetSymbolAddress((void**)&phi_k, g_phi_k);
    cudaGetSymbolAddress((void**)&vbuf,  g_v);
    cudaGetSymbolAddress((void**)&Sb,    g_S);
    cudaGetSymbolAddress((void**)&zb,    g_z);
    cudaGetSymbolAddress((void**)&xhi,   g_x_hi);
    cudaGetSymbolAddress((void**)&xlo,   g_x_lo);
    cudaGetSymbolAddress((void**)&ahi,   g_attn_hi);
    cudaGetSymbolAddress((void**)&whi,   g_w_hi);

    (void)cudaFuncSetAttribute(chunk_local_tc,
                               cudaFuncAttributeMaxDynamicSharedMemorySize, CL_SMEM);
    (void)cudaFuncSetAttribute(chunk_out_kernel,
                               cudaFuncAttributeMaxDynamicSharedMemorySize, CO_SMEM);
    (void)cudaFuncSetAttribute(gemm_f16split<0>,
                               cudaFuncAttributeMaxDynamicSharedMemorySize, GEMM_SMEM);
    (void)cudaFuncSetAttribute(gemm_f16split<1>,
                               cudaFuncAttributeMaxDynamicSharedMemorySize, GEMM_SMEM);
    (void)cudaFuncSetAttribute(gemm_f16split<2>,
                               cudaFuncAttributeMaxDynamicSharedMemorySize, GEMM_SMEM);

    // ---- splits ----
    const int nx4 = (MTOT * E_) / 4;
    split_kernel<<<(nx4 + 255) / 256, 256>>>(x, xhi, xlo, nx4);
    const int nw4 = (E_ * E_) / 4;
    const size_t wsz = (size_t)E_ * E_;
    dim3 gws((nw4 + 255) / 256, 4);
    wsplit_kernel<<<gws, 256>>>(Wq, Wk, Wv, Wo, whi, nw4);

    // ---- QK projection (2-term, fused q+k, elu): N = 2048 ----
    dim3 gqk(2 * E_ / 128, MTOT / 128), gb(256);
    gemm_f16split<1><<<gqk, gb, GEMM_SMEM>>>(xhi, xlo, whi, nullptr,
                                             phi_q, phi_k, MTOT, 2 * E_, E_);
    // ---- V projection (1-term, plain): N = 1024 ----
    dim3 gv(E_ / 128, MTOT / 128);
    gemm_f16split<2><<<gv, gb, GEMM_SMEM>>>(xhi, xhi, whi + 2 * wsz, nullptr,
                                            vbuf, nullptr, MTOT, E_, E_);

    // ---- chunked linear attention ----
    dim3 gc(NC_, H_, B_);
    chunk_local_tc<<<gc, 256, CL_SMEM>>>(phi_k, vbuf, Sb, zb);
    dim3 gp(B_ * H_, 16);
    prefix_kernel<<<gp, 256>>>(Sb, zb);
    chunk_out_kernel<<<gc, 256, CO_SMEM>>>(phi_q, phi_k, vbuf, Sb, zb, ahi);

    // ---- output projection (1-term) + bias ----
    dim3 gout(E_ / 128, MTOT / 128);
    gemm_f16split<0><<<gout, gb, GEMM_SMEM>>>(ahi, ahi, whi + 3 * wsz,
                                              bo, out, nullptr, MTOT, E_, E_);
}